// round 3
// baseline (speedup 1.0000x reference)
#include <cuda_runtime.h>
#include <math.h>

#define NN 50000
#define EE 800000

// ---------------- scratch (device globals; no allocations allowed) ----------------
__device__ float g_xw[(size_t)NN * 256];          // [N,256]: cols 0..127 = x@W0, 128..255 = x@W1
__device__ float g_as0[NN * 8], g_ad0[NN * 8], g_as1[NN * 8], g_ad1[NN * 8];
__device__ int g_src1[EE], g_dst1[EE], g_src2[EE], g_dst2[EE];
__device__ int g_deg1[NN], g_deg2[NN];
__device__ int g_start1[NN + 1], g_start2[NN + 1];
__device__ int g_cur1[NN], g_cur2[NN];
__device__ int g_csr1[EE], g_csr2[EE];
__device__ int g_is64;

// ---------------- packed f32x2 FMA (Blackwell FFMA2, PTX-only) ----------------
__device__ __forceinline__ void ffma2(float2& d, float2 a, float2 b) {
    unsigned long long& dd = reinterpret_cast<unsigned long long&>(d);
    unsigned long long aa = reinterpret_cast<unsigned long long&>(a);
    unsigned long long bb = reinterpret_cast<unsigned long long&>(b);
    asm("fma.rn.f32x2 %0, %1, %2, %0;" : "+l"(dd) : "l"(aa), "l"(bb));
}

// ---------------- edge-index dtype detection ----------------
__global__ void detect_kernel(const int* __restrict__ ei32) {
    int t = threadIdx.x;                  // 32 threads check odd 32-bit words
    int v = ei32[2 * t + 1];
    unsigned b = __ballot_sync(0xffffffffu, v != 0);
    if (t == 0) g_is64 = (b == 0) ? 1 : 0;
}

__global__ void zero_kernel() {
    int i = blockIdx.x * blockDim.x + threadIdx.x;
    if (i < NN) { g_deg1[i] = 0; g_deg2[i] = 0; g_cur1[i] = 0; g_cur2[i] = 0; }
}

// edges: hop1 (row,col), hop2 (row[col], col[col]); degree counts via atomics
__global__ void prep_kernel(const void* __restrict__ ei) {
    int e = blockIdx.x * blockDim.x + threadIdx.x;
    if (e >= EE) return;
    int s, d, s2, d2;
    if (g_is64) {
        const long long* r = (const long long*)ei;
        s = (int)r[e]; d = (int)r[EE + e];
        s2 = (int)r[d]; d2 = (int)r[EE + d];
    } else {
        const int* r = (const int*)ei;
        s = r[e]; d = r[EE + e];
        s2 = r[d]; d2 = r[EE + d];
    }
    g_src1[e] = s; g_dst1[e] = d;
    g_src2[e] = s2; g_dst2[e] = d2;
    atomicAdd(&g_deg1[d], 1);
    atomicAdd(&g_deg2[d2], 1);
}

// ---------------- exclusive scan (single block, 1024 threads) ----------------
__device__ void scan_exclusive(const int* __restrict__ deg, int* __restrict__ start) {
    __shared__ int warpsum[32];
    __shared__ int s_carry, s_total;
    int t = threadIdx.x, lane = t & 31, w = t >> 5;
    if (t == 0) s_carry = 0;
    __syncthreads();
    for (int base = 0; base < NN; base += 1024) {
        int i = base + t;
        int v = (i < NN) ? deg[i] : 0;
        int incl = v;
        #pragma unroll
        for (int o = 1; o < 32; o <<= 1) {
            int u = __shfl_up_sync(0xffffffffu, incl, o);
            if (lane >= o) incl += u;
        }
        if (lane == 31) warpsum[w] = incl;
        __syncthreads();
        if (t < 32) {
            int ws = warpsum[t];
            int wi = ws;
            #pragma unroll
            for (int o = 1; o < 32; o <<= 1) {
                int u = __shfl_up_sync(0xffffffffu, wi, o);
                if (t >= o) wi += u;
            }
            warpsum[t] = wi - ws;     // exclusive warp offset
            if (t == 31) s_total = wi;
        }
        __syncthreads();
        if (i < NN) start[i] = s_carry + warpsum[w] + incl - v;
        __syncthreads();
        if (t == 0) s_carry += s_total;
        __syncthreads();
    }
    if (t == 0) start[NN] = s_carry;
    __syncthreads();
}

__global__ void scan_kernel() {
    scan_exclusive(g_deg1, g_start1);
    scan_exclusive(g_deg2, g_start2);
}

__global__ void scatter_kernel() {
    int e = blockIdx.x * blockDim.x + threadIdx.x;
    if (e >= EE) return;
    {
        int d = g_dst1[e];
        int slot = g_start1[d] + atomicAdd(&g_cur1[d], 1);
        g_csr1[slot] = g_src1[e];
    }
    {
        int d = g_dst2[e];
        int slot = g_start2[d] + atomicAdd(&g_cur2[d], 1);
        g_csr2[slot] = g_src2[e];
    }
}

// ---------------- GEMM: xw = x @ [W0|W1], fp32 with packed f32x2 FMA ----------------
// block tile 64(M) x 128(N), K-tile 32; 256 threads, 4x8 outputs/thread (as float2 pairs)
__global__ __launch_bounds__(256) void gemm_kernel(const float* __restrict__ x,
                                                   const float* __restrict__ W0,
                                                   const float* __restrict__ W1) {
    __shared__ float As[32][68];    // [K][M] transposed, pad 4 -> conflict-light
    __shared__ float Bs[32][132];   // [K][N], pad 4
    const float* __restrict__ W = blockIdx.y ? W1 : W0;
    int rowbase = blockIdx.x * 64;
    int coff = blockIdx.y * 128;
    int tid = threadIdx.x;
    int tx = tid & 15, ty = tid >> 4;
    int lane = tid & 31, warp = tid >> 5;
    int jb = tid & 127, kb0 = tid >> 7;

    float2 acc[4][4];
    #pragma unroll
    for (int i = 0; i < 4; i++)
        #pragma unroll
        for (int q = 0; q < 4; q++) acc[i][q] = make_float2(0.f, 0.f);

    for (int kb = 0; kb < 256; kb += 32) {
        #pragma unroll
        for (int r = warp; r < 64; r += 8) {
            int row = rowbase + r;
            As[lane][r] = (row < NN) ? x[(size_t)row * 256 + kb + lane] : 0.f;
        }
        #pragma unroll
        for (int k = kb0; k < 32; k += 2) {
            Bs[k][jb] = W[(size_t)(kb + k) * 128 + jb];
        }
        __syncthreads();
        #pragma unroll
        for (int kk = 0; kk < 32; kk++) {
            float4 b0 = *(const float4*)&Bs[kk][tx * 8];
            float4 b1 = *(const float4*)&Bs[kk][tx * 8 + 4];
            float2 bq0 = make_float2(b0.x, b0.y), bq1 = make_float2(b0.z, b0.w);
            float2 bq2 = make_float2(b1.x, b1.y), bq3 = make_float2(b1.z, b1.w);
            #pragma unroll
            for (int i = 0; i < 4; i++) {
                float a = As[kk][ty * 4 + i];
                float2 a2 = make_float2(a, a);
                ffma2(acc[i][0], a2, bq0);
                ffma2(acc[i][1], a2, bq1);
                ffma2(acc[i][2], a2, bq2);
                ffma2(acc[i][3], a2, bq3);
            }
        }
        __syncthreads();
    }
    #pragma unroll
    for (int i = 0; i < 4; i++) {
        int row = rowbase + ty * 4 + i;
        if (row < NN) {
            float4 o0 = make_float4(acc[i][0].x, acc[i][0].y, acc[i][1].x, acc[i][1].y);
            float4 o1 = make_float4(acc[i][2].x, acc[i][2].y, acc[i][3].x, acc[i][3].y);
            *(float4*)&g_xw[(size_t)row * 256 + coff + tx * 8] = o0;
            *(float4*)&g_xw[(size_t)row * 256 + coff + tx * 8 + 4] = o1;
        }
    }
}

// ---------------- per-node attention logits ----------------
__global__ void att_kernel(const float* __restrict__ as0, const float* __restrict__ ad0,
                           const float* __restrict__ as1, const float* __restrict__ ad1) {
    int idx = blockIdx.x * blockDim.x + threadIdx.x;
    if (idx >= NN * 8) return;
    int n = idx >> 3, h = idx & 7;
    const float* r0 = g_xw + (size_t)n * 256 + h * 16;
    const float* r1 = r0 + 128;
    float s0 = 0.f, d0 = 0.f, s1 = 0.f, d1 = 0.f;
    #pragma unroll
    for (int c = 0; c < 16; c++) {
        float v0 = r0[c], v1 = r1[c];
        s0 += v0 * as0[h * 16 + c];
        d0 += v0 * ad0[h * 16 + c];
        s1 += v1 * as1[h * 16 + c];
        d1 += v1 * ad1[h * 16 + c];
    }
    g_as0[idx] = s0; g_ad0[idx] = d0; g_as1[idx] = s1; g_ad1[idx] = d1;
}

// ---------------- per-dst segment softmax + weighted aggregation ----------------
// one block (128 threads) per dst node.
// selfmult: multiplicity of the self-loop edge. Hop 1 = 1.0. Hop 2 = 2.0 because the
// reference appends self loops to (nr, nc) AND _gat_conv appends them again -> each
// node has TWO identical self-loop edges in the hop-2 softmax.
__global__ __launch_bounds__(128) void agg_kernel(int hop, float selfmult,
                                                  const float* __restrict__ bias,
                                                  float* __restrict__ out) {
    const int* __restrict__ start = hop ? g_start2 : g_start1;
    const int* __restrict__ csr   = hop ? g_csr2 : g_csr1;
    const float* __restrict__ a_s = hop ? g_as1 : g_as0;
    const float* __restrict__ a_d = hop ? g_ad1 : g_ad0;
    int off = hop ? 128 : 0;

    int dst = blockIdx.x;
    int t = threadIdx.x;
    __shared__ float red[128];
    __shared__ float sm_m[8], sm_is[8];
    __shared__ float adl[8];
    int s0 = start[dst];
    int deg = start[dst + 1] - s0;
    if (t < 8) adl[t] = a_d[dst * 8 + t];
    __syncthreads();

    int h = t & 7, j = t >> 3;
    // pass 1: per-head max over edges (+ self loop at e==deg; duplicates don't change max)
    float mx = -1e30f;
    for (int e = j; e <= deg; e += 16) {
        int src = (e < deg) ? csr[s0 + e] : dst;
        float v = a_s[src * 8 + h] + adl[h];
        v = v > 0.f ? v : 0.2f * v;
        mx = fmaxf(mx, v);
    }
    red[t] = mx; __syncthreads();
    #pragma unroll
    for (int o = 64; o >= 8; o >>= 1) { if (t < o) red[t] = fmaxf(red[t], red[t + o]); __syncthreads(); }
    if (t < 8) sm_m[t] = red[t];
    __syncthreads();

    // pass 2: per-head sum of exp (self loop counted selfmult times)
    float sum = 0.f;
    float mh = sm_m[h];
    for (int e = j; e <= deg; e += 16) {
        int src = (e < deg) ? csr[s0 + e] : dst;
        float v = a_s[src * 8 + h] + adl[h];
        v = v > 0.f ? v : 0.2f * v;
        float p = expf(v - mh);
        sum += (e < deg) ? p : selfmult * p;
    }
    red[t] = sum; __syncthreads();
    #pragma unroll
    for (int o = 64; o >= 8; o >>= 1) { if (t < o) red[t] += red[t + o]; __syncthreads(); }
    if (t < 8) sm_is[t] = 1.f / red[t];
    __syncthreads();

    // pass 3: weighted feature aggregation; thread t owns output channel t
    int hh = t >> 4;
    float mh2 = sm_m[hh], is = sm_is[hh], ad = adl[hh];
    const float* __restrict__ xwb = g_xw + off + t;
    float acc = 0.f;
    for (int e = 0; e <= deg; e++) {
        int src = (e < deg) ? csr[s0 + e] : dst;
        float v = a_s[src * 8 + hh] + ad;
        v = v > 0.f ? v : 0.2f * v;
        float al = expf(v - mh2) * is;
        if (e == deg) al *= selfmult;
        acc += al * xwb[(size_t)src * 256];
    }
    out[(size_t)dst * 256 + off + t] = acc + bias[t];
}

// ---------------- residual + LayerNorm (in place on d_out) ----------------
__global__ __launch_bounds__(256) void ln_kernel(float* __restrict__ out, const float* __restrict__ x,
                                                 const float* __restrict__ gamma,
                                                 const float* __restrict__ beta) {
    int n = blockIdx.x, t = threadIdx.x;
    size_t idx = (size_t)n * 256 + t;
    float v = out[idx] + x[idx];
    float s = v, q = v * v;
    #pragma unroll
    for (int o = 16; o; o >>= 1) {
        s += __shfl_xor_sync(0xffffffffu, s, o);
        q += __shfl_xor_sync(0xffffffffu, q, o);
    }
    __shared__ float ws[8], wq[8];
    int w = t >> 5, lane = t & 31;
    if (lane == 0) { ws[w] = s; wq[w] = q; }
    __syncthreads();
    if (t == 0) {
        float S = 0.f, Q = 0.f;
        #pragma unroll
        for (int i = 0; i < 8; i++) { S += ws[i]; Q += wq[i]; }
        ws[0] = S; wq[0] = Q;
    }
    __syncthreads();
    float mu = ws[0] * (1.f / 256.f);
    float var = wq[0] * (1.f / 256.f) - mu * mu;
    float rs = rsqrtf(var + 1e-5f);
    out[idx] = (v - mu) * rs * gamma[t] + beta[t];
}

// ---------------- launch ----------------
extern "C" void kernel_launch(void* const* d_in, const int* in_sizes, int n_in,
                              void* d_out, int out_size) {
    const float* x     = (const float*)d_in[0];
    const void*  ei    = d_in[1];
    const float* W0    = (const float*)d_in[2];
    const float* as0   = (const float*)d_in[3];
    const float* ad0   = (const float*)d_in[4];
    const float* b0    = (const float*)d_in[5];
    const float* W1    = (const float*)d_in[6];
    const float* as1   = (const float*)d_in[7];
    const float* ad1   = (const float*)d_in[8];
    const float* b1    = (const float*)d_in[9];
    const float* gamma = (const float*)d_in[10];
    const float* beta  = (const float*)d_in[11];
    float* out = (float*)d_out;

    detect_kernel<<<1, 32>>>((const int*)ei);
    zero_kernel<<<(NN + 255) / 256, 256>>>();
    prep_kernel<<<(EE + 255) / 256, 256>>>(ei);
    scan_kernel<<<1, 1024>>>();
    scatter_kernel<<<(EE + 255) / 256, 256>>>();
    gemm_kernel<<<dim3((NN + 63) / 64, 2), 256>>>(x, W0, W1);
    att_kernel<<<(NN * 8 + 255) / 256, 256>>>(as0, ad0, as1, ad1);
    agg_kernel<<<NN, 128>>>(0, 1.0f, b0, out);
    agg_kernel<<<NN, 128>>>(1, 2.0f, b1, out);
    ln_kernel<<<NN, 256>>>(out, x, gamma, beta);
}

// round 4
// speedup vs baseline: 1.2331x; 1.2331x over previous
#include <cuda_runtime.h>
#include <math.h>

#define NN 50000
#define EE 800000
#define NBLK 49   // ceil(NN/1024)

// ---------------- scratch (device globals; no allocations allowed) ----------------
__device__ float g_xw[(size_t)NN * 256];          // [N,256]: cols 0..127 = x@W0, 128..255 = x@W1
__device__ float g_as0[NN * 8], g_ad0[NN * 8], g_as1[NN * 8], g_ad1[NN * 8];
__device__ int g_src1[EE], g_dst1[EE], g_src2[EE], g_dst2[EE];
__device__ int g_deg1[NN], g_deg2[NN];
__device__ int g_start1[NN + 1], g_start2[NN + 1];
__device__ int g_cur1[NN], g_cur2[NN];
__device__ int g_csr1[EE], g_csr2[EE];
__device__ int g_bsum[2][64], g_boff[2][64];
__device__ int g_is64;

// ---------------- packed f32x2 FMA (Blackwell FFMA2, PTX-only) ----------------
__device__ __forceinline__ void ffma2(float2& d, float2 a, float2 b) {
    unsigned long long& dd = reinterpret_cast<unsigned long long&>(d);
    unsigned long long aa = reinterpret_cast<unsigned long long&>(a);
    unsigned long long bb = reinterpret_cast<unsigned long long&>(b);
    asm("fma.rn.f32x2 %0, %1, %2, %0;" : "+l"(dd) : "l"(aa), "l"(bb));
}

// ---------------- zero + edge-index dtype detection (fused) ----------------
__global__ void zero_kernel(const int* __restrict__ ei32) {
    int i = blockIdx.x * blockDim.x + threadIdx.x;
    if (i < NN) { g_deg1[i] = 0; g_deg2[i] = 0; g_cur1[i] = 0; g_cur2[i] = 0; }
    if (blockIdx.x == 0 && threadIdx.x < 32) {
        int v = ei32[2 * threadIdx.x + 1];   // odd 32-bit words are 0 iff int64 (ids < 2^31)
        unsigned b = __ballot_sync(0xffffffffu, v != 0);
        if (threadIdx.x == 0) g_is64 = (b == 0) ? 1 : 0;
    }
}

// edges: hop1 (row,col), hop2 (row[col], col[col]); degree counts via atomics
__global__ void prep_kernel(const void* __restrict__ ei) {
    int e = blockIdx.x * blockDim.x + threadIdx.x;
    if (e >= EE) return;
    int s, d, s2, d2;
    if (g_is64) {
        const long long* r = (const long long*)ei;
        s = (int)r[e]; d = (int)r[EE + e];
        s2 = (int)r[d]; d2 = (int)r[EE + d];
    } else {
        const int* r = (const int*)ei;
        s = r[e]; d = r[EE + e];
        s2 = r[d]; d2 = r[EE + d];
    }
    g_src1[e] = s; g_dst1[e] = d;
    g_src2[e] = s2; g_dst2[e] = d2;
    atomicAdd(&g_deg1[d], 1);
    atomicAdd(&g_deg2[d2], 1);
}

// ---------------- 3-stage parallel exclusive scan ----------------
// stage 1: per-block scan (49 blocks x 2 arrays)
__global__ __launch_bounds__(1024) void scan1_kernel() {
    int arr = blockIdx.y;
    const int* __restrict__ deg = arr ? g_deg2 : g_deg1;
    int* __restrict__ start = arr ? g_start2 : g_start1;
    __shared__ int warpsum[32];
    int t = threadIdx.x, lane = t & 31, w = t >> 5;
    int i = blockIdx.x * 1024 + t;
    int v = (i < NN) ? deg[i] : 0;
    int incl = v;
    #pragma unroll
    for (int o = 1; o < 32; o <<= 1) {
        int u = __shfl_up_sync(0xffffffffu, incl, o);
        if (lane >= o) incl += u;
    }
    if (lane == 31) warpsum[w] = incl;
    __syncthreads();
    if (t < 32) {
        int ws = warpsum[t];
        int wi = ws;
        #pragma unroll
        for (int o = 1; o < 32; o <<= 1) {
            int u = __shfl_up_sync(0xffffffffu, wi, o);
            if (t >= o) wi += u;
        }
        warpsum[t] = wi - ws;          // exclusive warp offset
        if (t == 31) g_bsum[arr][blockIdx.x] = wi;   // block total
    }
    __syncthreads();
    if (i < NN) start[i] = warpsum[w] + incl - v;
}

// stage 2: scan the 49 block sums for both arrays (one tiny block)
__global__ void scan2_kernel() {
    __shared__ int sm[2][64];
    int t = threadIdx.x;            // 128 threads: t<64 arr0, t>=64 arr1
    int arr = t >> 6, i = t & 63;
    int v = (i < NBLK) ? g_bsum[arr][i] : 0;
    sm[arr][i] = v;
    __syncthreads();
    #pragma unroll
    for (int off = 1; off < 64; off <<= 1) {
        int add = (i >= off) ? sm[arr][i - off] : 0;
        __syncthreads();
        sm[arr][i] += add;
        __syncthreads();
    }
    g_boff[arr][i] = sm[arr][i] - v;   // exclusive block offset
    if (i == 63) {
        if (arr == 0) g_start1[NN] = sm[0][63];
        else          g_start2[NN] = sm[1][63];
    }
}

// stage 3: add block offsets
__global__ __launch_bounds__(1024) void scan3_kernel() {
    int arr = blockIdx.y;
    int* __restrict__ start = arr ? g_start2 : g_start1;
    int i = blockIdx.x * 1024 + threadIdx.x;
    if (i < NN) start[i] += g_boff[arr][blockIdx.x];
}

__global__ void scatter_kernel() {
    int e = blockIdx.x * blockDim.x + threadIdx.x;
    if (e >= EE) return;
    {
        int d = g_dst1[e];
        int slot = g_start1[d] + atomicAdd(&g_cur1[d], 1);
        g_csr1[slot] = g_src1[e];
    }
    {
        int d = g_dst2[e];
        int slot = g_start2[d] + atomicAdd(&g_cur2[d], 1);
        g_csr2[slot] = g_src2[e];
    }
}

// ---------------- GEMM: xw = x @ [W0|W1] + fused attention logits ----------------
// block tile 64(M) x 128(N), K-tile 32; 256 threads, 4x8 outputs/thread (as float2 pairs)
__global__ __launch_bounds__(256) void gemm_kernel(const float* __restrict__ x,
                                                   const float* __restrict__ W0,
                                                   const float* __restrict__ W1,
                                                   const float* __restrict__ as0,
                                                   const float* __restrict__ ad0,
                                                   const float* __restrict__ as1,
                                                   const float* __restrict__ ad1) {
    __shared__ float As[32][68];    // [K][M] transposed, pad 4
    __shared__ float Bs[32][132];   // [K][N], pad 4
    const float* __restrict__ W = blockIdx.y ? W1 : W0;
    int rowbase = blockIdx.x * 64;
    int coff = blockIdx.y * 128;
    int tid = threadIdx.x;
    int tx = tid & 15, ty = tid >> 4;
    int lane = tid & 31, warp = tid >> 5;
    int jb = tid & 127, kb0 = tid >> 7;

    float2 acc[4][4];
    #pragma unroll
    for (int i = 0; i < 4; i++)
        #pragma unroll
        for (int q = 0; q < 4; q++) acc[i][q] = make_float2(0.f, 0.f);

    for (int kb = 0; kb < 256; kb += 32) {
        #pragma unroll
        for (int r = warp; r < 64; r += 8) {
            int row = rowbase + r;
            As[lane][r] = (row < NN) ? x[(size_t)row * 256 + kb + lane] : 0.f;
        }
        #pragma unroll
        for (int k = kb0; k < 32; k += 2) {
            Bs[k][jb] = W[(size_t)(kb + k) * 128 + jb];
        }
        __syncthreads();
        #pragma unroll
        for (int kk = 0; kk < 32; kk++) {
            float4 b0 = *(const float4*)&Bs[kk][tx * 8];
            float4 b1 = *(const float4*)&Bs[kk][tx * 8 + 4];
            float2 bq0 = make_float2(b0.x, b0.y), bq1 = make_float2(b0.z, b0.w);
            float2 bq2 = make_float2(b1.x, b1.y), bq3 = make_float2(b1.z, b1.w);
            #pragma unroll
            for (int i = 0; i < 4; i++) {
                float a = As[kk][ty * 4 + i];
                float2 a2 = make_float2(a, a);
                ffma2(acc[i][0], a2, bq0);
                ffma2(acc[i][1], a2, bq1);
                ffma2(acc[i][2], a2, bq2);
                ffma2(acc[i][3], a2, bq3);
            }
        }
        __syncthreads();
    }

    // attention vectors for this hop's half; thread tx owns cols tx*8..tx*8+7,
    // all inside head (tx>>1); within-head channel base = (tx&1)*8.
    const float* __restrict__ avs = blockIdx.y ? as1 : as0;
    const float* __restrict__ avd = blockIdx.y ? ad1 : ad0;
    float* __restrict__ gas = blockIdx.y ? g_as1 : g_as0;
    float* __restrict__ gad = blockIdx.y ? g_ad1 : g_ad0;
    int head = tx >> 1;
    int sub = (tx & 1) * 8;
    float4 v0 = *(const float4*)&avs[head * 16 + sub];
    float4 v1 = *(const float4*)&avs[head * 16 + sub + 4];
    float4 u0 = *(const float4*)&avd[head * 16 + sub];
    float4 u1 = *(const float4*)&avd[head * 16 + sub + 4];

    #pragma unroll
    for (int i = 0; i < 4; i++) {
        int row = rowbase + ty * 4 + i;
        float4 o0 = make_float4(acc[i][0].x, acc[i][0].y, acc[i][1].x, acc[i][1].y);
        float4 o1 = make_float4(acc[i][2].x, acc[i][2].y, acc[i][3].x, acc[i][3].y);
        if (row < NN) {
            *(float4*)&g_xw[(size_t)row * 256 + coff + tx * 8] = o0;
            *(float4*)&g_xw[(size_t)row * 256 + coff + tx * 8 + 4] = o1;
        }
        // fused attention logits: partial dot over this thread's 8 cols
        float s = o0.x * v0.x + o0.y * v0.y + o0.z * v0.z + o0.w * v0.w
                + o1.x * v1.x + o1.y * v1.y + o1.z * v1.z + o1.w * v1.w;
        float d = o0.x * u0.x + o0.y * u0.y + o0.z * u0.z + o0.w * u0.w
                + o1.x * u1.x + o1.y * u1.y + o1.z * u1.z + o1.w * u1.w;
        s += __shfl_xor_sync(0xffffffffu, s, 1);
        d += __shfl_xor_sync(0xffffffffu, d, 1);
        if ((tx & 1) == 0 && row < NN) {
            gas[row * 8 + head] = s;
            gad[row * 8 + head] = d;
        }
    }
}

// ---------------- per-dst segment softmax + weighted aggregation ----------------
// grid = 2*NN: blockIdx < NN -> hop 0, else hop 1. 128 threads per block.
// Online softmax merges the max and sum passes (2 gather passes instead of 3).
// selfmult: hop 1 = 1, hop 2 = 2 (reference double-appends self loops on hop 2).
__global__ __launch_bounds__(128) void agg_kernel(const float* __restrict__ b0,
                                                  const float* __restrict__ b1,
                                                  float* __restrict__ out) {
    int hop = (blockIdx.x >= NN) ? 1 : 0;
    int dst = blockIdx.x - hop * NN;
    const int* __restrict__ start = hop ? g_start2 : g_start1;
    const int* __restrict__ csr   = hop ? g_csr2 : g_csr1;
    const float* __restrict__ a_s = hop ? g_as1 : g_as0;
    const float* __restrict__ a_d = hop ? g_ad1 : g_ad0;
    const float* __restrict__ bias = hop ? b1 : b0;
    float selfmult = hop ? 2.0f : 1.0f;
    int off = hop ? 128 : 0;

    int t = threadIdx.x;
    __shared__ float redm[128], reds[128];
    __shared__ float sm_m[8], sm_is[8];
    __shared__ float adl[8];
    int s0 = start[dst];
    int deg = start[dst + 1] - s0;
    if (t < 8) adl[t] = a_d[dst * 8 + t];
    __syncthreads();

    int h = t & 7, j = t >> 3;
    // single online pass: running (max m, scaled sum s) per (j-group, head)
    float m = -1e30f, sum = 0.f;
    float ad = adl[h];
    for (int e = j; e <= deg; e += 16) {
        int src = (e < deg) ? csr[s0 + e] : dst;
        float v = a_s[src * 8 + h] + ad;
        v = v > 0.f ? v : 0.2f * v;
        float w = (e < deg) ? 1.0f : selfmult;
        float nm = fmaxf(m, v);
        sum = sum * __expf(m - nm) + w * __expf(v - nm);
        m = nm;
    }
    redm[t] = m; reds[t] = sum;
    __syncthreads();
    #pragma unroll
    for (int o = 64; o >= 8; o >>= 1) {
        if (t < o) {
            float m1 = redm[t], m2 = redm[t + o];
            float M = fmaxf(m1, m2);
            reds[t] = reds[t] * __expf(m1 - M) + reds[t + o] * __expf(m2 - M);
            redm[t] = M;
        }
        __syncthreads();
    }
    if (t < 8) { sm_m[t] = redm[t]; sm_is[t] = 1.f / reds[t]; }
    __syncthreads();

    // weighted feature aggregation; thread t owns output channel t
    int hh = t >> 4;
    float mh2 = sm_m[hh], is = sm_is[hh], ad2 = adl[hh];
    const float* __restrict__ xwb = g_xw + off + t;
    float acc = 0.f;
    #pragma unroll 4
    for (int e = 0; e <= deg; e++) {
        int src = (e < deg) ? csr[s0 + e] : dst;
        float v = a_s[src * 8 + hh] + ad2;
        v = v > 0.f ? v : 0.2f * v;
        float al = __expf(v - mh2) * is;
        if (e == deg) al *= selfmult;
        acc += al * xwb[(size_t)src * 256];
    }
    out[(size_t)dst * 256 + off + t] = acc + bias[t];
}

// ---------------- residual + LayerNorm (in place on d_out) ----------------
__global__ __launch_bounds__(256) void ln_kernel(float* __restrict__ out, const float* __restrict__ x,
                                                 const float* __restrict__ gamma,
                                                 const float* __restrict__ beta) {
    int n = blockIdx.x, t = threadIdx.x;
    size_t idx = (size_t)n * 256 + t;
    float v = out[idx] + x[idx];
    float s = v, q = v * v;
    #pragma unroll
    for (int o = 16; o; o >>= 1) {
        s += __shfl_xor_sync(0xffffffffu, s, o);
        q += __shfl_xor_sync(0xffffffffu, q, o);
    }
    __shared__ float ws[8], wq[8];
    int w = t >> 5, lane = t & 31;
    if (lane == 0) { ws[w] = s; wq[w] = q; }
    __syncthreads();
    if (t == 0) {
        float S = 0.f, Q = 0.f;
        #pragma unroll
        for (int i = 0; i < 8; i++) { S += ws[i]; Q += wq[i]; }
        ws[0] = S; wq[0] = Q;
    }
    __syncthreads();
    float mu = ws[0] * (1.f / 256.f);
    float var = wq[0] * (1.f / 256.f) - mu * mu;
    float rs = rsqrtf(var + 1e-5f);
    out[idx] = (v - mu) * rs * gamma[t] + beta[t];
}

// ---------------- launch ----------------
extern "C" void kernel_launch(void* const* d_in, const int* in_sizes, int n_in,
                              void* d_out, int out_size) {
    const float* x     = (const float*)d_in[0];
    const void*  ei    = d_in[1];
    const float* W0    = (const float*)d_in[2];
    const float* as0   = (const float*)d_in[3];
    const float* ad0   = (const float*)d_in[4];
    const float* b0    = (const float*)d_in[5];
    const float* W1    = (const float*)d_in[6];
    const float* as1   = (const float*)d_in[7];
    const float* ad1   = (const float*)d_in[8];
    const float* b1    = (const float*)d_in[9];
    const float* gamma = (const float*)d_in[10];
    const float* beta  = (const float*)d_in[11];
    float* out = (float*)d_out;

    zero_kernel<<<(NN + 255) / 256, 256>>>((const int*)ei);
    prep_kernel<<<(EE + 255) / 256, 256>>>(ei);
    scan1_kernel<<<dim3(NBLK, 2), 1024>>>();
    scan2_kernel<<<1, 128>>>();
    scan3_kernel<<<dim3(NBLK, 2), 1024>>>();
    scatter_kernel<<<(EE + 255) / 256, 256>>>();
    gemm_kernel<<<dim3((NN + 63) / 64, 2), 256>>>(x, W0, W1, as0, ad0, as1, ad1);
    agg_kernel<<<2 * NN, 128>>>(b0, b1, out);
    ln_kernel<<<NN, 256>>>(out, x, gamma, beta);
}

// round 7
// speedup vs baseline: 1.6726x; 1.3564x over previous
#include <cuda_runtime.h>
#include <math.h>

#define NN 50000
#define EE 800000
#define NBLK 49

// ---------------- scratch (device globals; no allocations allowed) ----------------
__device__ float g_xw[(size_t)NN * 256];          // [N,256]: cols 0..127 hop0, 128..255 hop1
__device__ float g_as0[NN * 8], g_ad0[NN * 8], g_as1[NN * 8], g_ad1[NN * 8];
__device__ int g_src1[EE], g_dst1[EE], g_src2[EE], g_dst2[EE];
__device__ int g_deg1[NN], g_deg2[NN];
__device__ int g_start1[NN + 1], g_start2[NN + 1];
__device__ int g_cur1[NN], g_cur2[NN];
__device__ int g_csr1[EE], g_csr2[EE];
__device__ int g_bsum[2][64], g_boff[2][64];
__device__ int g_is64;

// ---------------- packed f32x2 FMA (Blackwell FFMA2, PTX-only) ----------------
__device__ __forceinline__ void ffma2(float2& d, float2 a, float2 b) {
    unsigned long long& dd = reinterpret_cast<unsigned long long&>(d);
    unsigned long long aa = reinterpret_cast<unsigned long long&>(a);
    unsigned long long bb = reinterpret_cast<unsigned long long&>(b);
    asm("fma.rn.f32x2 %0, %1, %2, %0;" : "+l"(dd) : "l"(aa), "l"(bb));
}

// ---------------- zero + edge-index dtype detection (fused) ----------------
__global__ void zero_kernel(const int* __restrict__ ei32) {
    int i = blockIdx.x * blockDim.x + threadIdx.x;
    if (i < NN) { g_deg1[i] = 0; g_deg2[i] = 0; g_cur1[i] = 0; g_cur2[i] = 0; }
    if (blockIdx.x == 0 && threadIdx.x < 32) {
        int v = ei32[2 * threadIdx.x + 1];   // odd words 0 iff int64 (ids < 2^31)
        unsigned b = __ballot_sync(0xffffffffu, v != 0);
        if (threadIdx.x == 0) g_is64 = (b == 0) ? 1 : 0;
    }
}

// edges: hop1 (row,col), hop2 (row[col], col[col]); degree counts via atomics
__global__ void prep_kernel(const void* __restrict__ ei) {
    int e = blockIdx.x * blockDim.x + threadIdx.x;
    if (e >= EE) return;
    int s, d, s2, d2;
    if (g_is64) {
        const long long* r = (const long long*)ei;
        s = (int)r[e]; d = (int)r[EE + e];
        s2 = (int)r[d]; d2 = (int)r[EE + d];
    } else {
        const int* r = (const int*)ei;
        s = r[e]; d = r[EE + e];
        s2 = r[d]; d2 = r[EE + d];
    }
    g_src1[e] = s; g_dst1[e] = d;
    g_src2[e] = s2; g_dst2[e] = d2;
    atomicAdd(&g_deg1[d], 1);
    atomicAdd(&g_deg2[d2], 1);
}

// ---------------- 3-stage parallel exclusive scan ----------------
__global__ __launch_bounds__(1024) void scan1_kernel() {
    int arr = blockIdx.y;
    const int* __restrict__ deg = arr ? g_deg2 : g_deg1;
    int* __restrict__ start = arr ? g_start2 : g_start1;
    __shared__ int warpsum[32];
    int t = threadIdx.x, lane = t & 31, w = t >> 5;
    int i = blockIdx.x * 1024 + t;
    int v = (i < NN) ? deg[i] : 0;
    int incl = v;
    #pragma unroll
    for (int o = 1; o < 32; o <<= 1) {
        int u = __shfl_up_sync(0xffffffffu, incl, o);
        if (lane >= o) incl += u;
    }
    if (lane == 31) warpsum[w] = incl;
    __syncthreads();
    if (t < 32) {
        int ws = warpsum[t];
        int wi = ws;
        #pragma unroll
        for (int o = 1; o < 32; o <<= 1) {
            int u = __shfl_up_sync(0xffffffffu, wi, o);
            if (t >= o) wi += u;
        }
        warpsum[t] = wi - ws;
        if (t == 31) g_bsum[arr][blockIdx.x] = wi;
    }
    __syncthreads();
    if (i < NN) start[i] = warpsum[w] + incl - v;
}

__global__ void scan2_kernel() {
    __shared__ int sm[2][64];
    int t = threadIdx.x;
    int arr = t >> 6, i = t & 63;
    int v = (i < NBLK) ? g_bsum[arr][i] : 0;
    sm[arr][i] = v;
    __syncthreads();
    #pragma unroll
    for (int off = 1; off < 64; off <<= 1) {
        int add = (i >= off) ? sm[arr][i - off] : 0;
        __syncthreads();
        sm[arr][i] += add;
        __syncthreads();
    }
    g_boff[arr][i] = sm[arr][i] - v;
    if (i == 63) {
        if (arr == 0) g_start1[NN] = sm[0][63];
        else          g_start2[NN] = sm[1][63];
    }
}

__global__ __launch_bounds__(1024) void scan3_kernel() {
    int arr = blockIdx.y;
    int* __restrict__ start = arr ? g_start2 : g_start1;
    int i = blockIdx.x * 1024 + threadIdx.x;
    if (i < NN) start[i] += g_boff[arr][blockIdx.x];
}

__global__ void scatter_kernel() {
    int e = blockIdx.x * blockDim.x + threadIdx.x;
    if (e >= EE) return;
    {
        int d = g_dst1[e];
        int slot = g_start1[d] + atomicAdd(&g_cur1[d], 1);
        g_csr1[slot] = g_src1[e];
    }
    {
        int d = g_dst2[e];
        int slot = g_start2[d] + atomicAdd(&g_cur2[d], 1);
        g_csr2[slot] = g_src2[e];
    }
}

// ---------------- GEMM: xw = x @ [W0|W1] + fused attention logits ----------------
// block tile 64(M) x 128(N), K-tile 32; 256 threads, 4x8 outputs/thread (as float2 pairs)
__global__ __launch_bounds__(256) void gemm_kernel(const float* __restrict__ x,
                                                   const float* __restrict__ W0,
                                                   const float* __restrict__ W1,
                                                   const float* __restrict__ as0,
                                                   const float* __restrict__ ad0,
                                                   const float* __restrict__ as1,
                                                   const float* __restrict__ ad1) {
    __shared__ float As[32][68];    // [K][M] transposed, pad 4
    __shared__ float Bs[32][132];   // [K][N], pad 4
    const float* __restrict__ W = blockIdx.y ? W1 : W0;
    int rowbase = blockIdx.x * 64;
    int coff = blockIdx.y * 128;
    int tid = threadIdx.x;
    int tx = tid & 15, ty = tid >> 4;
    int lane = tid & 31, warp = tid >> 5;
    int jb = tid & 127, kb0 = tid >> 7;

    float2 acc[4][4];
    #pragma unroll
    for (int i = 0; i < 4; i++)
        #pragma unroll
        for (int q = 0; q < 4; q++) acc[i][q] = make_float2(0.f, 0.f);

    for (int kb = 0; kb < 256; kb += 32) {
        #pragma unroll
        for (int r = warp; r < 64; r += 8) {
            int row = rowbase + r;
            As[lane][r] = (row < NN) ? x[(size_t)row * 256 + kb + lane] : 0.f;
        }
        #pragma unroll
        for (int k = kb0; k < 32; k += 2) {
            Bs[k][jb] = W[(size_t)(kb + k) * 128 + jb];
        }
        __syncthreads();
        #pragma unroll
        for (int kk = 0; kk < 32; kk++) {
            float4 b0 = *(const float4*)&Bs[kk][tx * 8];
            float4 b1 = *(const float4*)&Bs[kk][tx * 8 + 4];
            float2 bq0 = make_float2(b0.x, b0.y), bq1 = make_float2(b0.z, b0.w);
            float2 bq2 = make_float2(b1.x, b1.y), bq3 = make_float2(b1.z, b1.w);
            #pragma unroll
            for (int i = 0; i < 4; i++) {
                float a = As[kk][ty * 4 + i];
                float2 a2 = make_float2(a, a);
                ffma2(acc[i][0], a2, bq0);
                ffma2(acc[i][1], a2, bq1);
                ffma2(acc[i][2], a2, bq2);
                ffma2(acc[i][3], a2, bq3);
            }
        }
        __syncthreads();
    }

    // attention vectors for this hop's half; thread tx owns cols tx*8..tx*8+7,
    // all inside head (tx>>1); within-head channel base = (tx&1)*8.
    const float* __restrict__ avs = blockIdx.y ? as1 : as0;
    const float* __restrict__ avd = blockIdx.y ? ad1 : ad0;
    float* __restrict__ gas = blockIdx.y ? g_as1 : g_as0;
    float* __restrict__ gad = blockIdx.y ? g_ad1 : g_ad0;
    int head = tx >> 1;
    int sub = (tx & 1) * 8;
    float4 v0 = *(const float4*)&avs[head * 16 + sub];
    float4 v1 = *(const float4*)&avs[head * 16 + sub + 4];
    float4 u0 = *(const float4*)&avd[head * 16 + sub];
    float4 u1 = *(const float4*)&avd[head * 16 + sub + 4];

    #pragma unroll
    for (int i = 0; i < 4; i++) {
        int row = rowbase + ty * 4 + i;
        float4 o0 = make_float4(acc[i][0].x, acc[i][0].y, acc[i][1].x, acc[i][1].y);
        float4 o1 = make_float4(acc[i][2].x, acc[i][2].y, acc[i][3].x, acc[i][3].y);
        if (row < NN) {
            *(float4*)&g_xw[(size_t)row * 256 + coff + tx * 8] = o0;
            *(float4*)&g_xw[(size_t)row * 256 + coff + tx * 8 + 4] = o1;
        }
        // fused attention logits: partial dot over this thread's 8 cols
        float s = o0.x * v0.x + o0.y * v0.y + o0.z * v0.z + o0.w * v0.w
                + o1.x * v1.x + o1.y * v1.y + o1.z * v1.z + o1.w * v1.w;
        float d = o0.x * u0.x + o0.y * u0.y + o0.z * u0.z + o0.w * u0.w
                + o1.x * u1.x + o1.y * u1.y + o1.z * u1.z + o1.w * u1.w;
        s += __shfl_xor_sync(0xffffffffu, s, 1);
        d += __shfl_xor_sync(0xffffffffu, d, 1);
        if ((tx & 1) == 0 && row < NN) {
            gas[row * 8 + head] = s;
            gad[row * 8 + head] = d;
        }
    }
}

// ---------------- warp-per-dst segment softmax + weighted aggregation ----------------
// 8 warps per block, one (hop,dst) per warp; no __syncthreads.
// selfmult: hop 1 = 1, hop 2 = 2 (reference double-appends self loops on hop 2).
__global__ __launch_bounds__(256) void agg_kernel(const float* __restrict__ b0,
                                                  const float* __restrict__ b1,
                                                  float* __restrict__ out) {
    int gw = blockIdx.x * 8 + (threadIdx.x >> 5);
    if (gw >= 2 * NN) return;
    int hop = (gw >= NN) ? 1 : 0;
    int dst = gw - hop * NN;
    int lane = threadIdx.x & 31;
    const int* __restrict__ start = hop ? g_start2 : g_start1;
    const int* __restrict__ csr   = hop ? g_csr2 : g_csr1;
    const float* __restrict__ a_s = hop ? g_as1 : g_as0;
    const float* __restrict__ a_d = hop ? g_ad1 : g_ad0;
    const float* __restrict__ bias = hop ? b1 : b0;
    float selfmult = hop ? 2.0f : 1.0f;

    int s0 = start[dst];
    int deg = start[dst + 1] - s0;

    // online softmax: lane = h + 8*j  (8 heads x 4 edge-groups)
    int h = lane & 7, j = lane >> 3;
    float ad_h = a_d[dst * 8 + h];
    float m = -1e30f, sum = 0.f;
    for (int e = j; e <= deg; e += 4) {
        int src = (e < deg) ? csr[s0 + e] : dst;
        float v = a_s[src * 8 + h] + ad_h;
        v = v > 0.f ? v : 0.2f * v;
        float w = (e < deg) ? 1.0f : selfmult;
        float nm = fmaxf(m, v);
        sum = sum * __expf(m - nm) + w * __expf(v - nm);
        m = nm;
    }
    #pragma unroll
    for (int o = 8; o <= 16; o <<= 1) {
        float om = __shfl_xor_sync(0xffffffffu, m, o);
        float os = __shfl_xor_sync(0xffffffffu, sum, o);
        float nm = fmaxf(m, om);
        sum = sum * __expf(m - nm) + os * __expf(om - nm);
        m = nm;
    }

    // pass 2: lane owns 4 channels [lane*4, lane*4+4) of this hop's 128; head = lane>>2
    int hh = lane >> 2;
    float mh = __shfl_sync(0xffffffffu, m, hh);
    float is = 1.f / __shfl_sync(0xffffffffu, sum, hh);
    float adh = __shfl_sync(0xffffffffu, ad_h, hh);
    int off4 = hop ? 32 : 0;
    const float4* __restrict__ xw4 = (const float4*)g_xw;
    float4 acc = make_float4(0.f, 0.f, 0.f, 0.f);
    for (int e = 0; e <= deg; e++) {
        int src = (e < deg) ? csr[s0 + e] : dst;
        float v = a_s[src * 8 + hh] + adh;
        v = v > 0.f ? v : 0.2f * v;
        float al = __expf(v - mh) * is;
        if (e == deg) al *= selfmult;
        float4 f = xw4[(size_t)src * 64 + off4 + lane];
        acc.x += al * f.x; acc.y += al * f.y; acc.z += al * f.z; acc.w += al * f.w;
    }
    float4 bv = ((const float4*)bias)[lane];
    acc.x += bv.x; acc.y += bv.y; acc.z += bv.z; acc.w += bv.w;
    ((float4*)out)[(size_t)dst * 64 + off4 + lane] = acc;
}

// ---------------- residual + LayerNorm (in place on d_out) ----------------
__global__ __launch_bounds__(256) void ln_kernel(float* __restrict__ out, const float* __restrict__ x,
                                                 const float* __restrict__ gamma,
                                                 const float* __restrict__ beta) {
    int n = blockIdx.x, t = threadIdx.x;
    size_t idx = (size_t)n * 256 + t;
    float v = out[idx] + x[idx];
    float s = v, q = v * v;
    #pragma unroll
    for (int o = 16; o; o >>= 1) {
        s += __shfl_xor_sync(0xffffffffu, s, o);
        q += __shfl_xor_sync(0xffffffffu, q, o);
    }
    __shared__ float ws[8], wq[8];
    int w = t >> 5, lane = t & 31;
    if (lane == 0) { ws[w] = s; wq[w] = q; }
    __syncthreads();
    if (t == 0) {
        float S = 0.f, Q = 0.f;
        #pragma unroll
        for (int i = 0; i < 8; i++) { S += ws[i]; Q += wq[i]; }
        ws[0] = S; wq[0] = Q;
    }
    __syncthreads();
    float mu = ws[0] * (1.f / 256.f);
    float var = wq[0] * (1.f / 256.f) - mu * mu;
    float rs = rsqrtf(var + 1e-5f);
    out[idx] = (v - mu) * rs * gamma[t] + beta[t];
}

// ---------------- launch ----------------
extern "C" void kernel_launch(void* const* d_in, const int* in_sizes, int n_in,
                              void* d_out, int out_size) {
    const float* x     = (const float*)d_in[0];
    const void*  ei    = d_in[1];
    const float* W0    = (const float*)d_in[2];
    const float* as0   = (const float*)d_in[3];
    const float* ad0   = (const float*)d_in[4];
    const float* b0    = (const float*)d_in[5];
    const float* W1    = (const float*)d_in[6];
    const float* as1   = (const float*)d_in[7];
    const float* ad1   = (const float*)d_in[8];
    const float* b1    = (const float*)d_in[9];
    const float* gamma = (const float*)d_in[10];
    const float* beta  = (const float*)d_in[11];
    float* out = (float*)d_out;

    zero_kernel<<<(NN + 255) / 256, 256>>>((const int*)ei);
    prep_kernel<<<(EE + 255) / 256, 256>>>(ei);
    scan1_kernel<<<dim3(NBLK, 2), 1024>>>();
    scan2_kernel<<<1, 128>>>();
    scan3_kernel<<<dim3(NBLK, 2), 1024>>>();
    scatter_kernel<<<(EE + 255) / 256, 256>>>();
    gemm_kernel<<<dim3((NN + 63) / 64, 2), 256>>>(x, W0, W1, as0, ad0, as1, ad1);
    agg_kernel<<<(2 * NN + 7) / 8, 256>>>(b0, b1, out);
    ln_kernel<<<NN, 256>>>(out, x, gamma, beta);
}